// round 2
// baseline (speedup 1.0000x reference)
#include <cuda_runtime.h>
#include <cstdint>

#define BATCH 16
#define NF 64
#define FIN 192
#define HW 4096
#define IM 64
#define STEPS 16
#define EPSV 1e-5f

#define EMB_SLICE (BATCH*NF*HW)           /* 4,194,304 */
#define N_CLIP (BATCH*3*HW)               /* 196,608   */
#define OFF_EMB N_CLIP
#define OFF_RAW (OFF_EMB + 17*EMB_SLICE)  /* 71,499,776 */

// ---- device scratch (static allocation: allowed; no cudaMalloc anywhere) ----
__device__ float g_w[BATCH*NF*FIN];       // w[b][o][c]
__device__ float g_bias[BATCH*NF];        // b[b][o]
__device__ float g_mu[BATCH*FIN];
__device__ float g_rs[BATCH*FIN];         // rsqrt(var+eps)
__device__ float g_sobel[BATCH*128*HW];   // [b][0..63]=sobelx, [64..127]=sobely (33.5 MB)

// packed f32x2 FMA (sm_100+): 2 fp32 FMAs per issue slot -> full 128 FMA/cyc/SM
__device__ __forceinline__ void ffma2(unsigned long long& d, unsigned long long a, unsigned long long b) {
    asm("fma.rn.f32x2 %0, %1, %2, %0;" : "+l"(d) : "l"(a), "l"(b));
}

// ---------------------------------------------------------------------------
// w[b][o][c] = sum_k lat[b,k] * Wk[k, o*192+c] + bk[o*192+c]
__global__ void k_weights(const float* __restrict__ lat, const float* __restrict__ Wk,
                          const float* __restrict__ bk) {
    __shared__ float ls[512];
    int b = blockIdx.y;
    int j = blockIdx.x * 256 + threadIdx.x;   // 0..12287
    for (int k = threadIdx.x; k < 512; k += 256) ls[k] = lat[b*512 + k];
    __syncthreads();
    float acc = bk[j];
#pragma unroll 8
    for (int k = 0; k < 512; k++) acc += ls[k] * Wk[(size_t)k*12288 + j];
    g_w[(size_t)b*12288 + j] = acc;
}

__global__ void k_bias(const float* __restrict__ lat, const float* __restrict__ Wb,
                       const float* __restrict__ bb) {
    __shared__ float ls[512];
    int b = blockIdx.x;
    int o = threadIdx.x;                      // 64 threads
    for (int k = o; k < 512; k += 64) ls[k] = lat[b*512 + k];
    __syncthreads();
    float acc = bb[o];
#pragma unroll 8
    for (int k = 0; k < 512; k++) acc += ls[k] * Wb[k*64 + o];
    g_bias[b*64 + o] = acc;
}

// emb slice 0 = out0: zeros except channel 0, pixel (32,32) = 1
__global__ void k_init(float* __restrict__ emb0) {
    int idx = blockIdx.x * 256 + threadIdx.x;
    int within = idx & (NF*HW - 1);           // c*4096 + px
    emb0[idx] = (within == (32*64 + 32)) ? 1.0f : 0.0f;
}

// ---------------------------------------------------------------------------
// 3-value block reduction (256 threads). After the call every thread holds the sums.
__device__ __forceinline__ void reduce3(float& a, float& b, float& c,
                                        float (*red)[8], int tid) {
#pragma unroll
    for (int off = 16; off; off >>= 1) {
        a += __shfl_down_sync(0xffffffffu, a, off);
        b += __shfl_down_sync(0xffffffffu, b, off);
        c += __shfl_down_sync(0xffffffffu, c, off);
    }
    __syncthreads();                       // make red reusable across calls
    int w = tid >> 5, l = tid & 31;
    if (l == 0) { red[0][w] = a; red[1][w] = b; red[2][w] = c; }
    __syncthreads();
    a = b = c = 0.f;
#pragma unroll
    for (int i = 0; i < 8; i++) { a += red[0][i]; b += red[1][i]; c += red[2][i]; }
}

// Per (b, source-channel): compute Sobel-x/y (zero-padded SAME), materialize them,
// and produce mean + rsqrt(var+eps) for the 3 derived perception channels.
__global__ void __launch_bounds__(256) k_stats(const float* __restrict__ embt) {
    __shared__ float img[HW];
    __shared__ float red[3][8];
    int b = blockIdx.y, c = blockIdx.x, tid = threadIdx.x;
    const float* src = embt + ((size_t)(b*NF + c)) * HW;
    for (int i = tid; i < HW; i += 256) img[i] = src[i];
    __syncthreads();

    float sxv[16], syv[16];
    float s0 = 0.f, s1 = 0.f, s2 = 0.f;
#pragma unroll
    for (int k = 0; k < 16; k++) {
        int px = k*256 + tid;
        int y = px >> 6, x = px & 63;
        float v  = img[px];
        float na = (y > 0  && x > 0 ) ? img[px-65] : 0.f;  // (y-1,x-1)
        float nb = (y > 0            ) ? img[px-64] : 0.f; // (y-1,x)
        float nc = (y > 0  && x < 63) ? img[px-63] : 0.f;  // (y-1,x+1)
        float nd = (           x > 0 ) ? img[px-1]  : 0.f; // (y,x-1)
        float ne = (           x < 63) ? img[px+1]  : 0.f; // (y,x+1)
        float nf = (y < 63 && x > 0 ) ? img[px+63] : 0.f;  // (y+1,x-1)
        float ng = (y < 63           ) ? img[px+64] : 0.f; // (y+1,x)
        float nh = (y < 63 && x < 63) ? img[px+65] : 0.f;  // (y+1,x+1)
        float sx = (nc - na + 2.f*(ne - nd) + nh - nf) * 0.125f;
        float sy = (nf - na + 2.f*(ng - nb) + nh - nc) * 0.125f;
        sxv[k] = sx; syv[k] = sy;
        s0 += v; s1 += sx; s2 += sy;
    }
    float* gx = g_sobel + ((size_t)(b*128 + c)) * HW;
    float* gy = g_sobel + ((size_t)(b*128 + 64 + c)) * HW;
#pragma unroll
    for (int k = 0; k < 16; k++) { int px = k*256 + tid; gx[px] = sxv[k]; gy[px] = syv[k]; }

    reduce3(s0, s1, s2, red, tid);
    const float inv = 1.0f / HW;
    float mu0 = s0*inv, mu1 = s1*inv, mu2 = s2*inv;

    float q0 = 0.f, q1 = 0.f, q2 = 0.f;   // two-pass variance (no cancellation)
#pragma unroll
    for (int k = 0; k < 16; k++) {
        int px = k*256 + tid;
        float d0 = img[px] - mu0;  q0 += d0*d0;
        float d1 = sxv[k]  - mu1;  q1 += d1*d1;
        float d2 = syv[k]  - mu2;  q2 += d2*d2;
    }
    reduce3(q0, q1, q2, red, tid);
    if (tid == 0) {
        int base = b*FIN + c;
        g_mu[base]       = mu0;  g_rs[base]       = rsqrtf(q0*inv + EPSV);
        g_mu[base + 64]  = mu1;  g_rs[base + 64]  = rsqrtf(q1*inv + EPSV);
        g_mu[base + 128] = mu2;  g_rs[base + 128] = rsqrtf(q2*inv + EPSV);
    }
}

// ---------------------------------------------------------------------------
// Per (batch, 128-pixel tile): C[128px,64o] = sum_c norm(p)[c,px] * w[o,c];
// out_new = out_old + leak*(C + bias); writes next emb slice.
__device__ __forceinline__ void load_tiles(const float* __restrict__ embt, int b, int px0,
                                           int c0, int tid, const float* __restrict__ mu,
                                           const float* __restrict__ rs,
                                           float av[8], float wv[4]) {
#pragma unroll
    for (int r = 0; r < 8; r++) {
        int lin = r*256 + tid;
        int cc = lin >> 7, p = lin & 127;
        int c = c0 + cc;
        const float* src = (c < 64) ? (embt + ((size_t)(b*NF + c))*HW)
                                    : (g_sobel + ((size_t)(b*128 + (c - 64)))*HW);
        float v = src[px0 + p];
        av[r] = (v - mu[c]) * rs[c];
    }
#pragma unroll
    for (int r = 0; r < 4; r++) {
        int lin = r*256 + tid;
        int o = lin >> 4, cc = lin & 15;
        wv[r] = g_w[((size_t)(b*NF + o))*FIN + c0 + cc];
    }
}

__global__ void __launch_bounds__(256) k_gemm(const float* __restrict__ embt,
                                              float* __restrict__ embt1,
                                              const float* __restrict__ leak_ptr) {
    __shared__ float a_s[2][16][128];                 // 16 KB
    __shared__ unsigned long long w_s[2][16][64];     // 16 KB (weight duplicated into f32x2)
    int b = blockIdx.y;
    int px0 = blockIdx.x * 128;
    int tid = threadIdx.x;
    int tx = tid & 31, ty = tid >> 5;
    const float* mu = g_mu + b*FIN;
    const float* rs = g_rs + b*FIN;

    unsigned long long acc[16];
#pragma unroll
    for (int i = 0; i < 16; i++) acc[i] = 0ull;

    float av[8], wv[4];
    load_tiles(embt, b, px0, 0, tid, mu, rs, av, wv);

    for (int ch = 0; ch < 12; ch++) {
        int buf = ch & 1;
#pragma unroll
        for (int r = 0; r < 8; r++) {
            int lin = r*256 + tid;
            a_s[buf][lin >> 7][lin & 127] = av[r];
        }
#pragma unroll
        for (int r = 0; r < 4; r++) {
            int lin = r*256 + tid;
            unsigned int u = __float_as_uint(wv[r]);
            w_s[buf][lin & 15][lin >> 4] = ((unsigned long long)u << 32) | u;
        }
        __syncthreads();
        if (ch < 11) load_tiles(embt, b, px0, (ch + 1)*16, tid, mu, rs, av, wv);
#pragma unroll
        for (int kk = 0; kk < 16; kk++) {
            unsigned long long ap0 = *(const unsigned long long*)&a_s[buf][kk][2*tx];
            unsigned long long ap1 = *(const unsigned long long*)&a_s[buf][kk][64 + 2*tx];
#pragma unroll
            for (int o = 0; o < 8; o++) {
                unsigned long long wvv = w_s[buf][kk][ty*8 + o];
                ffma2(acc[o*2],     ap0, wvv);
                ffma2(acc[o*2 + 1], ap1, wvv);
            }
        }
        __syncthreads();   // single barrier per chunk is sufficient with 2 buffers
    }

    float leak = *leak_ptr;
    leak = fminf(fmaxf(leak, 0.001f), 1000.0f);
#pragma unroll
    for (int o = 0; o < 8; o++) {
        int oo = ty*8 + o;
        float bo = g_bias[b*NF + oo];
        const float2* oldp = (const float2*)(embt  + ((size_t)(b*NF + oo))*HW + px0);
        float2*       newp = (float2*)      (embt1 + ((size_t)(b*NF + oo))*HW + px0);
        float lo0 = __uint_as_float((unsigned)(acc[o*2]     & 0xffffffffu));
        float hi0 = __uint_as_float((unsigned)(acc[o*2]     >> 32));
        float lo1 = __uint_as_float((unsigned)(acc[o*2 + 1] & 0xffffffffu));
        float hi1 = __uint_as_float((unsigned)(acc[o*2 + 1] >> 32));
        float2 o0 = oldp[tx];       // pixels 2tx, 2tx+1
        float2 o1 = oldp[32 + tx];  // pixels 64+2tx, 65+2tx
        float2 n0, n1;
        n0.x = o0.x + leak*(lo0 + bo);
        n0.y = o0.y + leak*(hi0 + bo);
        n1.x = o1.x + leak*(lo1 + bo);
        n1.y = o1.y + leak*(hi1 + bo);
        newp[tx] = n0;
        newp[32 + tx] = n1;
    }
}

// clipped RGB + raw RGB from the final state
__global__ void k_final(const float* __restrict__ emb_final, float* __restrict__ out) {
    int idx = blockIdx.x * 256 + threadIdx.x;     // < 196608
    int b = idx / (3*HW);
    int rem = idx - b*3*HW;
    int c = rem >> 12;
    int px = rem & 4095;
    float v = emb_final[((size_t)(b*NF + c))*HW + px];
    out[(size_t)OFF_RAW + idx] = v;
    out[idx] = fminf(fmaxf(v, -1.0f), 1.0f);
}

// ---------------------------------------------------------------------------
extern "C" void kernel_launch(void* const* d_in, const int* in_sizes, int n_in,
                              void* d_out, int out_size) {
    const float* lat  = (const float*)d_in[0];
    const float* Wk   = (const float*)d_in[1];
    const float* bk   = (const float*)d_in[2];
    const float* Wb   = (const float*)d_in[3];
    const float* bb   = (const float*)d_in[4];
    const float* leak = (const float*)d_in[5];
    float* out = (float*)d_out;

    k_weights<<<dim3(48, 16), 256>>>(lat, Wk, bk);
    k_bias<<<16, 64>>>(lat, Wb, bb);
    k_init<<<EMB_SLICE/256, 256>>>(out + OFF_EMB);

    for (int t = 0; t < STEPS; t++) {
        const float* et  = out + (size_t)OFF_EMB + (size_t)t * EMB_SLICE;
        float*       et1 = out + (size_t)OFF_EMB + (size_t)(t + 1) * EMB_SLICE;
        k_stats<<<dim3(64, 16), 256>>>(et);
        k_gemm<<<dim3(32, 16), 256>>>(et, et1, leak);
    }
    k_final<<<N_CLIP/256, 256>>>(out + OFF_EMB + (size_t)16*EMB_SLICE, out);
}